// round 2
// baseline (speedup 1.0000x reference)
#include <cuda_runtime.h>
#include <cuda_bf16.h>
#include <math.h>

// LearnableTD: backward lambda-return scan.
//   B=8192 rows, T=1024 steps. One warp per row; each lane owns 4 consecutive
//   timesteps; affine suffix scan via shfl composes the linear recurrence:
//     lr_t = a_t + b_t * lr_{t+1},  a_t = r_t + gamma*(1-lam_t)*(1-done_t)*v_{t+1}
//     sr_t = r_t + b_t * sr_{t+1},  b_t = gamma*lam_t*(1-done_t)
// Output layout: [lambda_returns (B, T+1) | sum_rewards (B, T)], float32.

static constexpr int B_ROWS = 8192;
static constexpr int T_LEN  = 1024;
static constexpr int VSTRIDE = T_LEN + 1;   // 1025

__global__ __launch_bounds__(256) void td_kernel(
    const float* __restrict__ values,     // [B, T+1]
    const float* __restrict__ rewards,    // [B, T]
    const float* __restrict__ dones,      // [B, T]
    const float* __restrict__ raw_gamma,  // [1]
    const float* __restrict__ raw_lambd,  // [T]
    const int*   __restrict__ start_idx,  // [1] or nullptr
    float* __restrict__ out)              // [B*(T+1) + B*T]
{
    // --- Per-CTA coefficient tables in shared memory ---------------------
    __shared__ __align__(16) float s_glam[T_LEN];  // gamma * lambda_t
    __shared__ __align__(16) float s_gom[T_LEN];   // gamma * (1 - lambda_t)
    {
        const float gamma = fmaxf(tanhf(raw_gamma[0]), 0.0f);
        const int s = (start_idx != nullptr) ? start_idx[0] : 0;
        #pragma unroll
        for (int i = 0; i < T_LEN / 256; ++i) {
            const int t = i * 256 + threadIdx.x;
            const float lam = fmaxf(tanhf(__ldg(raw_lambd + s + t)), 0.0f);
            s_glam[t] = gamma * lam;
            s_gom[t]  = gamma * (1.0f - lam);
        }
    }
    __syncthreads();

    const int warp = (blockIdx.x * blockDim.x + threadIdx.x) >> 5;
    const int lane = threadIdx.x & 31;

    const float* __restrict__ vrow = values  + (size_t)warp * VSTRIDE;
    const float* __restrict__ rrow = rewards + (size_t)warp * T_LEN;
    const float* __restrict__ drow = dones   + (size_t)warp * T_LEN;
    float* __restrict__ lrout = out + (size_t)warp * VSTRIDE;
    float* __restrict__ srout = out + (size_t)B_ROWS * VSTRIDE + (size_t)warp * T_LEN;

    const float vT = __ldg(vrow + T_LEN);
    if (lane == 0) lrout[T_LEN] = vT;   // lambda_returns[:, T] = values[:, T]

    float carry_l = vT;     // lr value entering current chunk from above
    float carry_s = 0.0f;   // sr value entering current chunk from above
    const unsigned FULL = 0xffffffffu;

    // 8 chunks of 128 timesteps, processed high-t -> low-t.
    #pragma unroll 2
    for (int c = T_LEN / 128 - 1; c >= 0; --c) {
        const int tb = c * 128 + 4 * lane;   // lane's earliest t in this chunk

        // Coalesced vector loads; coeff tables from smem (conflict-free LDS.128).
        const float4 r4 = *reinterpret_cast<const float4*>(rrow + tb);
        const float4 d4 = *reinterpret_cast<const float4*>(drow + tb);
        const float4 gl = *reinterpret_cast<const float4*>(s_glam + tb);
        const float4 go = *reinterpret_cast<const float4*>(s_gom + tb);
        // values rows have stride 1025 floats; lanes cover a contiguous
        // 128-float span offset by +1 -> coalesced scalar LDG (sector-merged).
        const float v0 = vrow[tb + 1];
        const float v1 = vrow[tb + 2];
        const float v2 = vrow[tb + 3];
        const float v3 = vrow[tb + 4];

        // Per-element affine coefficients: x_t = a_t + b_t * x_{t+1}
        const float nd0 = 1.0f - d4.x, nd1 = 1.0f - d4.y;
        const float nd2 = 1.0f - d4.z, nd3 = 1.0f - d4.w;
        const float b0 = gl.x * nd0, b1 = gl.y * nd1;
        const float b2 = gl.z * nd2, b3 = gl.w * nd3;
        const float al0 = fmaf(go.x * nd0, v0, r4.x);
        const float al1 = fmaf(go.y * nd1, v1, r4.y);
        const float al2 = fmaf(go.z * nd2, v2, r4.z);
        const float al3 = fmaf(go.w * nd3, v3, r4.w);
        // sr stream: a_t = r_t, same b_t.

        // Lane-local compose: transform mapping carry@(tb+4) -> value@tb.
        float Al = al3, As = r4.w, Bc = b3;
        Al = fmaf(b2, Al, al2);  As = fmaf(b2, As, r4.z);  Bc *= b2;
        Al = fmaf(b1, Al, al1);  As = fmaf(b1, As, r4.y);  Bc *= b1;
        Al = fmaf(b0, Al, al0);  As = fmaf(b0, As, r4.x);  Bc *= b0;

        // Warp suffix scan: lane i ends covering lanes i..31.
        #pragma unroll
        for (int d = 1; d < 32; d <<= 1) {
            const float tAl = __shfl_down_sync(FULL, Al, d);
            const float tAs = __shfl_down_sync(FULL, As, d);
            const float tB  = __shfl_down_sync(FULL, Bc, d);
            if (lane + d < 32) {
                Al = fmaf(Bc, tAl, Al);
                As = fmaf(Bc, tAs, As);
                Bc *= tB;
            }
        }

        // Value at this lane's earliest element (t = tb).
        const float vl = fmaf(Bc, carry_l, Al);
        const float vs = fmaf(Bc, carry_s, As);

        // Carry entering this lane (value at t = tb+4) = next lane's vl.
        float cin_l = __shfl_down_sync(FULL, vl, 1);
        float cin_s = __shfl_down_sync(FULL, vs, 1);
        if (lane == 31) { cin_l = carry_l; cin_s = carry_s; }

        // Serial replay for per-element outputs (4 steps, high t -> low t).
        const float l3 = fmaf(b3, cin_l, al3), s3 = fmaf(b3, cin_s, r4.w);
        const float l2 = fmaf(b2, l3, al2),    s2 = fmaf(b2, s3, r4.z);
        const float l1 = fmaf(b1, l2, al1),    s1 = fmaf(b1, s2, r4.y);
        const float l0 = fmaf(b0, l1, al0),    s0 = fmaf(b0, s1, r4.x);

        // sum_rewards rows 16B-aligned -> STG.128.
        *reinterpret_cast<float4*>(srout + tb) = make_float4(s0, s1, s2, s3);
        // lambda_returns rows stride-1025 -> contiguous scalar STG (merged).
        lrout[tb]     = l0;
        lrout[tb + 1] = l1;
        lrout[tb + 2] = l2;
        lrout[tb + 3] = l3;

        // Chunk carry for the next (earlier) chunk = value at chunk start.
        carry_l = __shfl_sync(FULL, vl, 0);
        carry_s = __shfl_sync(FULL, vs, 0);
    }
}

extern "C" void kernel_launch(void* const* d_in, const int* in_sizes, int n_in,
                              void* d_out, int out_size) {
    const float* values    = (const float*)d_in[0];
    const float* rewards   = (const float*)d_in[1];
    const float* dones     = (const float*)d_in[2];
    const float* raw_gamma = (const float*)d_in[3];
    const float* raw_lambd = (const float*)d_in[4];
    const int*   start_idx = (n_in > 5) ? (const int*)d_in[5] : nullptr;
    (void)in_sizes; (void)out_size;

    const int warps_per_block = 256 / 32;               // 8 rows per CTA
    const int grid = B_ROWS / warps_per_block;          // 1024 CTAs
    td_kernel<<<grid, 256>>>(values, rewards, dones,
                             raw_gamma, raw_lambd, start_idx, (float*)d_out);
}